// round 6
// baseline (speedup 1.0000x reference)
#include <cuda_runtime.h>
#include <stdint.h>

#define NN_MAX 50000
#define E_MAX  800000
#define D_IN 128
#define D_RNI 32
#define D_H0 160
#define H 256

// ---------------- scratch (static device globals; no allocs allowed) --------
__device__ __align__(16) float g_xt [NN_MAX * H];
__device__ __align__(16) float g_agg[NN_MAX * H];
__device__ __align__(16) float g_dis[NN_MAX];
__device__ __align__(16) int   g_deg[NN_MAX];
__device__ __align__(16) int   g_rowstart[NN_MAX];
__device__ __align__(16) int   g_cursor[NN_MAX];
__device__ __align__(16) int   g_csr_src[E_MAX];
__device__ int g_is64;

// ---------------- edge-index dtype detection ---------------------------------
__global__ void detect_kernel(const void* __restrict__ ei, int n) {
    if (threadIdx.x == 0 && blockIdx.x == 0) {
        const long long* p = (const long long*)ei;
        int ok = 1;
        for (int i = 0; i < 512; i++) {
            long long v = p[i];
            if (v < 0 || v >= (long long)n) { ok = 0; break; }
        }
        g_is64 = ok;
    }
}

__device__ __forceinline__ int load_idx(const void* ei, long long i, int is64) {
    return is64 ? (int)((const long long*)ei)[i] : ((const int*)ei)[i];
}

__global__ void count_deg_kernel(const void* __restrict__ ei, int* __restrict__ deg,
                                 int e, int n) {
    int idx = blockIdx.x * blockDim.x + threadIdx.x;
    if (idx >= e) return;
    int is64 = g_is64;
    int d = load_idx(ei, (long long)e + idx, is64);
    if (d >= 0 && d < n) atomicAdd(&deg[d], 1);
}

// warp-shuffle exclusive scan of deg -> row_start + cursor; also dis = rsqrt(deg+1)
__global__ void scan_dis_kernel(const int* __restrict__ deg, int* __restrict__ row_start,
                                int* __restrict__ cursor, float* __restrict__ dis, int n) {
    __shared__ int warpsum[32];
    int tid = threadIdx.x;
    int lane = tid & 31;
    int wid = tid >> 5;
    int carry = 0;
    for (int base = 0; base < n; base += 1024) {
        int i = base + tid;
        int v = (i < n) ? deg[i] : 0;
        int s = v;
#pragma unroll
        for (int off = 1; off < 32; off <<= 1) {
            int t = __shfl_up_sync(0xffffffff, s, off);
            if (lane >= off) s += t;
        }
        if (lane == 31) warpsum[wid] = s;
        __syncthreads();
        if (wid == 0) {
            int w = warpsum[lane];
#pragma unroll
            for (int off = 1; off < 32; off <<= 1) {
                int t = __shfl_up_sync(0xffffffff, w, off);
                if (lane >= off) w += t;
            }
            warpsum[lane] = w;
        }
        __syncthreads();
        int warp_excl = (wid == 0) ? 0 : warpsum[wid - 1];
        int total = warpsum[31];
        if (i < n) {
            int ex = carry + warp_excl + s - v;
            row_start[i] = ex;
            cursor[i] = ex;
            dis[i] = rsqrtf((float)v + 1.0f);
        }
        carry += total;
        __syncthreads();
    }
}

__global__ void csr_fill_kernel(const void* __restrict__ ei,
                                int* __restrict__ cursor, int* __restrict__ csr_src,
                                int e, int n) {
    int idx = blockIdx.x * blockDim.x + threadIdx.x;
    if (idx >= e) return;
    int is64 = g_is64;
    int d = load_idx(ei, (long long)e + idx, is64);
    int s = load_idx(ei, idx, is64);
    if (d < 0 || d >= n || s < 0 || s >= n) return;
    int p = atomicAdd(&cursor[d], 1);
    if (p >= 0 && p < E_MAX) csr_src[p] = s;
}

// gather-aggregate: 64 threads per node (float4 columns), 4 nodes per block.
__global__ void gather_kernel(const float* __restrict__ xt, const float* __restrict__ dis,
                              const int* __restrict__ row_start, const int* __restrict__ deg,
                              const int* __restrict__ csr_src, const float* __restrict__ bias,
                              float* __restrict__ agg, int n) {
    int node = blockIdx.x * 4 + (threadIdx.x >> 6);
    int c4 = threadIdx.x & 63;
    if (node >= n) return;
    int start = row_start[node];
    int d = deg[node];
    const float4* xt4 = reinterpret_cast<const float4*>(xt);

    float4 a0 = make_float4(0.f, 0.f, 0.f, 0.f);
    float4 a1 = make_float4(0.f, 0.f, 0.f, 0.f);
    int j = 0;
    for (; j + 2 <= d; j += 2) {
        int s0 = __ldg(&csr_src[start + j]);
        int s1 = __ldg(&csr_src[start + j + 1]);
        float w0 = __ldg(&dis[s0]);
        float w1 = __ldg(&dis[s1]);
        float4 v0 = __ldg(&xt4[(size_t)s0 * 64 + c4]);
        float4 v1 = __ldg(&xt4[(size_t)s1 * 64 + c4]);
        a0.x = fmaf(v0.x, w0, a0.x); a0.y = fmaf(v0.y, w0, a0.y);
        a0.z = fmaf(v0.z, w0, a0.z); a0.w = fmaf(v0.w, w0, a0.w);
        a1.x = fmaf(v1.x, w1, a1.x); a1.y = fmaf(v1.y, w1, a1.y);
        a1.z = fmaf(v1.z, w1, a1.z); a1.w = fmaf(v1.w, w1, a1.w);
    }
    if (j < d) {
        int s0 = __ldg(&csr_src[start + j]);
        float w0 = __ldg(&dis[s0]);
        float4 v0 = __ldg(&xt4[(size_t)s0 * 64 + c4]);
        a0.x = fmaf(v0.x, w0, a0.x); a0.y = fmaf(v0.y, w0, a0.y);
        a0.z = fmaf(v0.z, w0, a0.z); a0.w = fmaf(v0.w, w0, a0.w);
    }
    a0.x += a1.x; a0.y += a1.y; a0.z += a1.z; a0.w += a1.w;

    float dd = dis[node];
    float4 self = xt4[(size_t)node * 64 + c4];
    float4 b = reinterpret_cast<const float4*>(bias)[c4];
    float4 r;
    r.x = fmaf(dd, fmaf(self.x, dd, a0.x), b.x);
    r.y = fmaf(dd, fmaf(self.y, dd, a0.y), b.y);
    r.z = fmaf(dd, fmaf(self.z, dd, a0.z), b.z);
    r.w = fmaf(dd, fmaf(self.w, dd, a0.w), b.w);
    reinterpret_cast<float4*>(agg)[(size_t)node * 64 + c4] = r;
}

// ---------------- tf32x3 tensor-core GEMM, double-buffered smem ---------------
__device__ __forceinline__ uint32_t f2tf(float f) {
    uint32_t u;
    asm("cvt.rna.tf32.f32 %0, %1;" : "=r"(u) : "f"(f));
    return u;
}

__device__ __forceinline__ void split_tf32(float v, uint32_t& hi, uint32_t& lo) {
    hi = f2tf(v);
    lo = __float_as_uint(v - __uint_as_float(hi));
}

__device__ __forceinline__ void mma_tf32(float (&d)[4], const uint32_t (&a)[4],
                                         const uint32_t (&b)[2]) {
    asm("mma.sync.aligned.m16n8k8.row.col.f32.tf32.tf32.f32 "
        "{%0,%1,%2,%3}, {%4,%5,%6,%7}, {%8,%9}, {%0,%1,%2,%3};"
        : "+f"(d[0]), "+f"(d[1]), "+f"(d[2]), "+f"(d[3])
        : "r"(a[0]), "r"(a[1]), "r"(a[2]), "r"(a[3]), "r"(b[0]), "r"(b[1]));
}

#define APAD 20
#define BPAD 136
// stage layout (uint32 words): As_hi[128*20]=2560, As_lo=2560, Bs_hi[16*136]=2176, Bs_lo=2176
#define STAGE_WORDS 9472
#define GEMM_SMEM_BYTES (2 * STAGE_WORDS * 4)

template<bool SPLIT_A, bool RELU_IN, bool ADD_BIAS>
__global__ void __launch_bounds__(256, 2)
mma_gemm(const float* __restrict__ A, const float* __restrict__ A2,
         const float* __restrict__ B,
         const float* __restrict__ bias, float* __restrict__ C,
         int M, int N, int K) {
    extern __shared__ uint32_t sm[];

    const int tid  = threadIdx.x;
    const int lane = tid & 31;
    const int warp = tid >> 5;
    const int wm = warp & 3;
    const int wn = warp >> 2;
    const int g = lane >> 2;
    const int t = lane & 3;
    const int bm = blockIdx.y * 128;
    const int bn = blockIdx.x * 128;

    float acc[2][8][4];
#pragma unroll
    for (int mi = 0; mi < 2; mi++)
#pragma unroll
        for (int ni = 0; ni < 8; ni++)
#pragma unroll
            for (int r = 0; r < 4; r++) acc[mi][ni][r] = 0.0f;

    float4 pa[2], pb[2];

    auto load_tiles = [&](int k0) {
#pragma unroll
        for (int i = 0; i < 2; i++) {
            int idx = i * 256 + tid;
            int m  = idx >> 2;
            int col = k0 + ((idx & 3) << 2);
            int gm = bm + m;
            if (gm < M) {
                if (SPLIT_A) {
                    pa[i] = (col < D_IN)
                        ? *reinterpret_cast<const float4*>(A  + (size_t)gm * D_IN  + col)
                        : *reinterpret_cast<const float4*>(A2 + (size_t)gm * D_RNI + (col - D_IN));
                } else {
                    pa[i] = *reinterpret_cast<const float4*>(A + (size_t)gm * K + col);
                }
            } else {
                pa[i] = make_float4(0.f, 0.f, 0.f, 0.f);
            }
        }
#pragma unroll
        for (int i = 0; i < 2; i++) {
            int idx = i * 256 + tid;
            int kr = idx >> 5;
            int nq = (idx & 31) << 2;
            pb[i] = *reinterpret_cast<const float4*>(B + (size_t)(k0 + kr) * N + bn + nq);
        }
    };

    auto store_tiles = [&](int s) {
        uint32_t* As_hi = sm + s * STAGE_WORDS;
        uint32_t* As_lo = As_hi + 2560;
        uint32_t* Bs_hi = As_hi + 5120;
        uint32_t* Bs_lo = Bs_hi + 2176;
#pragma unroll
        for (int i = 0; i < 2; i++) {
            int idx = i * 256 + tid;
            int m  = idx >> 2;
            int kq = (idx & 3) << 2;
            float4 v = pa[i];
            if (RELU_IN) {
                v.x = fmaxf(v.x, 0.f); v.y = fmaxf(v.y, 0.f);
                v.z = fmaxf(v.z, 0.f); v.w = fmaxf(v.w, 0.f);
            }
            uint4 h, l;
            split_tf32(v.x, h.x, l.x); split_tf32(v.y, h.y, l.y);
            split_tf32(v.z, h.z, l.z); split_tf32(v.w, h.w, l.w);
            *reinterpret_cast<uint4*>(&As_hi[m * APAD + kq]) = h;
            *reinterpret_cast<uint4*>(&As_lo[m * APAD + kq]) = l;
        }
#pragma unroll
        for (int i = 0; i < 2; i++) {
            int idx = i * 256 + tid;
            int kr = idx >> 5;
            int nq = (idx & 31) << 2;
            float4 v = pb[i];
            uint4 h, l;
            split_tf32(v.x, h.x, l.x); split_tf32(v.y, h.y, l.y);
            split_tf32(v.z, h.z, l.z); split_tf32(v.w, h.w, l.w);
            *reinterpret_cast<uint4*>(&Bs_hi[kr * BPAD + nq]) = h;
            *reinterpret_cast<uint4*>(&Bs_lo[kr * BPAD + nq]) = l;
        }
    };

    auto compute = [&](int s) {
        uint32_t* As_hi = sm + s * STAGE_WORDS;
        uint32_t* As_lo = As_hi + 2560;
        uint32_t* Bs_hi = As_hi + 5120;
        uint32_t* Bs_lo = Bs_hi + 2176;
#pragma unroll
        for (int kk = 0; kk < 16; kk += 8) {
            uint32_t ah[2][4], al[2][4];
#pragma unroll
            for (int mi = 0; mi < 2; mi++) {
                int r0 = (wm * 32 + mi * 16 + g) * APAD;
                int r1 = r0 + 8 * APAD;
                int c0 = kk + t;
                int c1 = c0 + 4;
                ah[mi][0] = As_hi[r0 + c0]; ah[mi][1] = As_hi[r1 + c0];
                ah[mi][2] = As_hi[r0 + c1]; ah[mi][3] = As_hi[r1 + c1];
                al[mi][0] = As_lo[r0 + c0]; al[mi][1] = As_lo[r1 + c0];
                al[mi][2] = As_lo[r0 + c1]; al[mi][3] = As_lo[r1 + c1];
            }
#pragma unroll
            for (int ni = 0; ni < 8; ni++) {
                int ncol = wn * 64 + ni * 8 + g;
                int kr0 = (kk + t) * BPAD;
                int kr1 = kr0 + 4 * BPAD;
                uint32_t bh[2] = { Bs_hi[kr0 + ncol], Bs_hi[kr1 + ncol] };
                uint32_t bl[2] = { Bs_lo[kr0 + ncol], Bs_lo[kr1 + ncol] };
#pragma unroll
                for (int mi = 0; mi < 2; mi++) {
                    mma_tf32(acc[mi][ni], ah[mi], bh);
                    mma_tf32(acc[mi][ni], ah[mi], bl);
                    mma_tf32(acc[mi][ni], al[mi], bh);
                }
            }
        }
    };

    // prologue: fill stage 0
    load_tiles(0);
    store_tiles(0);
    __syncthreads();

    int cur = 0;
    for (int k0 = 0; k0 < K; k0 += 16) {
        bool has_next = (k0 + 16 < K);
        if (has_next) load_tiles(k0 + 16);   // issue LDGs early
        compute(cur);                         // hide LDG latency behind MMAs
        if (has_next) store_tiles(cur ^ 1);  // regs ready by now
        __syncthreads();
        cur ^= 1;
    }

#pragma unroll
    for (int mi = 0; mi < 2; mi++) {
#pragma unroll
        for (int ni = 0; ni < 8; ni++) {
            int row = bm + wm * 32 + mi * 16 + g;
            int col = bn + wn * 64 + ni * 8 + t * 2;
            float bx = 0.f, by = 0.f;
            if (ADD_BIAS) {
                float2 bb = *reinterpret_cast<const float2*>(bias + col);
                bx = bb.x; by = bb.y;
            }
            if (row < M) {
                float2 v = make_float2(acc[mi][ni][0] + bx, acc[mi][ni][1] + by);
                *reinterpret_cast<float2*>(C + (size_t)row * N + col) = v;
            }
            int row2 = row + 8;
            if (row2 < M) {
                float2 v = make_float2(acc[mi][ni][2] + bx, acc[mi][ni][3] + by);
                *reinterpret_cast<float2*>(C + (size_t)row2 * N + col) = v;
            }
        }
    }
}

// ---------------- launch ------------------------------------------------------
extern "C" void kernel_launch(void* const* d_in, const int* in_sizes, int n_in,
                              void* d_out, int out_size) {
    const float* x     = (const float*)d_in[0];
    const float* rni   = (const float*)d_in[1];
    const void*  ei    = d_in[2];
    const float* W1    = (const float*)d_in[3];
    const float* b1    = (const float*)d_in[4];
    const float* W2    = (const float*)d_in[5];
    const float* b2    = (const float*)d_in[6];
    const float* Wout  = (const float*)d_in[7];
    const float* bout  = (const float*)d_in[8];
    float* out = (float*)d_out;

    int n = in_sizes[0] / D_IN;
    int e = in_sizes[2] / 2;

    float *xt, *agg, *dis;
    int *deg, *row_start, *cursor, *csr_src;
    cudaGetSymbolAddress((void**)&xt,        g_xt);
    cudaGetSymbolAddress((void**)&agg,       g_agg);
    cudaGetSymbolAddress((void**)&dis,       g_dis);
    cudaGetSymbolAddress((void**)&deg,       g_deg);
    cudaGetSymbolAddress((void**)&row_start, g_rowstart);
    cudaGetSymbolAddress((void**)&cursor,    g_cursor);
    cudaGetSymbolAddress((void**)&csr_src,   g_csr_src);

    // allow >48KB dynamic smem for the GEMM (attribute set, not an allocation)
    cudaFuncSetAttribute(mma_gemm<true,  false, false>, cudaFuncAttributeMaxDynamicSharedMemorySize, GEMM_SMEM_BYTES);
    cudaFuncSetAttribute(mma_gemm<false, true,  false>, cudaFuncAttributeMaxDynamicSharedMemorySize, GEMM_SMEM_BYTES);
    cudaFuncSetAttribute(mma_gemm<false, true,  true >, cudaFuncAttributeMaxDynamicSharedMemorySize, GEMM_SMEM_BYTES);

    // prep (order chosen so the 4th kernel launch = mma_gemm for ncu capture)
    detect_kernel<<<1, 32>>>(ei, n);
    cudaMemsetAsync(deg, 0, (size_t)n * sizeof(int));
    count_deg_kernel<<<(e + 255) / 256, 256>>>(ei, deg, e, n);
    scan_dis_kernel<<<1, 1024>>>(deg, row_start, cursor, dis, n);

    dim3 gemm_grid(H / 128, (n + 127) / 128);
    int gather_grid = (n + 3) / 4;

    // layer 1 GEMM first (launch #4), CSR fill runs before gather needs it
    mma_gemm<true, false, false><<<gemm_grid, 256, GEMM_SMEM_BYTES>>>(x, rni, W1, nullptr, xt, n, H, D_H0);
    csr_fill_kernel<<<(e + 255) / 256, 256>>>(ei, cursor, csr_src, e, n);
    gather_kernel<<<gather_grid, 256>>>(xt, dis, row_start, deg, csr_src, b1, agg, n);

    // layer 2
    mma_gemm<false, true, false><<<gemm_grid, 256, GEMM_SMEM_BYTES>>>(agg, nullptr, W2, nullptr, xt, n, H, H);
    gather_kernel<<<gather_grid, 256>>>(xt, dis, row_start, deg, csr_src, b2, agg, n);

    // output
    mma_gemm<false, true, true><<<gemm_grid, 256, GEMM_SMEM_BYTES>>>(agg, nullptr, Wout, bout, out, n, H, H);
}

// round 7
// speedup vs baseline: 1.2642x; 1.2642x over previous
#include <cuda_runtime.h>
#include <stdint.h>

#define NN_MAX 50000
#define E_MAX  800000
#define D_IN 128
#define D_RNI 32
#define D_H0 160
#define H 256

// ---------------- scratch (static device globals; no allocs allowed) --------
__device__ __align__(16) float g_xt [NN_MAX * H];
__device__ __align__(16) float g_agg[NN_MAX * H];
__device__ __align__(16) float g_dis[NN_MAX];
__device__ __align__(16) int   g_deg[NN_MAX];
__device__ __align__(16) int   g_rowstart[NN_MAX];
__device__ __align__(16) int   g_cursor[NN_MAX];
__device__ __align__(16) int   g_csr_src[E_MAX];
__device__ int g_is64;

// ---------------- edge-index dtype detection ---------------------------------
__global__ void detect_kernel(const void* __restrict__ ei, int n) {
    if (threadIdx.x == 0 && blockIdx.x == 0) {
        const long long* p = (const long long*)ei;
        int ok = 1;
        for (int i = 0; i < 512; i++) {
            long long v = p[i];
            if (v < 0 || v >= (long long)n) { ok = 0; break; }
        }
        g_is64 = ok;
    }
}

__device__ __forceinline__ int load_idx(const void* ei, long long i, int is64) {
    return is64 ? (int)((const long long*)ei)[i] : ((const int*)ei)[i];
}

__global__ void count_deg_kernel(const void* __restrict__ ei, int* __restrict__ deg,
                                 int e, int n) {
    int idx = blockIdx.x * blockDim.x + threadIdx.x;
    if (idx >= e) return;
    int is64 = g_is64;
    int d = load_idx(ei, (long long)e + idx, is64);
    if (d >= 0 && d < n) atomicAdd(&deg[d], 1);
}

// warp-shuffle exclusive scan of deg -> row_start + cursor; also dis = rsqrt(deg+1)
__global__ void scan_dis_kernel(const int* __restrict__ deg, int* __restrict__ row_start,
                                int* __restrict__ cursor, float* __restrict__ dis, int n) {
    __shared__ int warpsum[32];
    int tid = threadIdx.x;
    int lane = tid & 31;
    int wid = tid >> 5;
    int carry = 0;
    for (int base = 0; base < n; base += 1024) {
        int i = base + tid;
        int v = (i < n) ? deg[i] : 0;
        int s = v;
#pragma unroll
        for (int off = 1; off < 32; off <<= 1) {
            int t = __shfl_up_sync(0xffffffff, s, off);
            if (lane >= off) s += t;
        }
        if (lane == 31) warpsum[wid] = s;
        __syncthreads();
        if (wid == 0) {
            int w = warpsum[lane];
#pragma unroll
            for (int off = 1; off < 32; off <<= 1) {
                int t = __shfl_up_sync(0xffffffff, w, off);
                if (lane >= off) w += t;
            }
            warpsum[lane] = w;
        }
        __syncthreads();
        int warp_excl = (wid == 0) ? 0 : warpsum[wid - 1];
        int total = warpsum[31];
        if (i < n) {
            int ex = carry + warp_excl + s - v;
            row_start[i] = ex;
            cursor[i] = ex;
            dis[i] = rsqrtf((float)v + 1.0f);
        }
        carry += total;
        __syncthreads();
    }
}

__global__ void csr_fill_kernel(const void* __restrict__ ei,
                                int* __restrict__ cursor, int* __restrict__ csr_src,
                                int e, int n) {
    int idx = blockIdx.x * blockDim.x + threadIdx.x;
    if (idx >= e) return;
    int is64 = g_is64;
    int d = load_idx(ei, (long long)e + idx, is64);
    int s = load_idx(ei, idx, is64);
    if (d < 0 || d >= n || s < 0 || s >= n) return;
    int p = atomicAdd(&cursor[d], 1);
    if (p >= 0 && p < E_MAX) csr_src[p] = s;
}

// gather-aggregate: 64 threads per node (float4 columns), 4 nodes per block.
__global__ void gather_kernel(const float* __restrict__ xt, const float* __restrict__ dis,
                              const int* __restrict__ row_start, const int* __restrict__ deg,
                              const int* __restrict__ csr_src, const float* __restrict__ bias,
                              float* __restrict__ agg, int n) {
    int node = blockIdx.x * 4 + (threadIdx.x >> 6);
    int c4 = threadIdx.x & 63;
    if (node >= n) return;
    int start = row_start[node];
    int d = deg[node];
    const float4* xt4 = reinterpret_cast<const float4*>(xt);

    float4 a0 = make_float4(0.f, 0.f, 0.f, 0.f);
    float4 a1 = make_float4(0.f, 0.f, 0.f, 0.f);
    int j = 0;
    for (; j + 2 <= d; j += 2) {
        int s0 = __ldg(&csr_src[start + j]);
        int s1 = __ldg(&csr_src[start + j + 1]);
        float w0 = __ldg(&dis[s0]);
        float w1 = __ldg(&dis[s1]);
        float4 v0 = __ldg(&xt4[(size_t)s0 * 64 + c4]);
        float4 v1 = __ldg(&xt4[(size_t)s1 * 64 + c4]);
        a0.x = fmaf(v0.x, w0, a0.x); a0.y = fmaf(v0.y, w0, a0.y);
        a0.z = fmaf(v0.z, w0, a0.z); a0.w = fmaf(v0.w, w0, a0.w);
        a1.x = fmaf(v1.x, w1, a1.x); a1.y = fmaf(v1.y, w1, a1.y);
        a1.z = fmaf(v1.z, w1, a1.z); a1.w = fmaf(v1.w, w1, a1.w);
    }
    if (j < d) {
        int s0 = __ldg(&csr_src[start + j]);
        float w0 = __ldg(&dis[s0]);
        float4 v0 = __ldg(&xt4[(size_t)s0 * 64 + c4]);
        a0.x = fmaf(v0.x, w0, a0.x); a0.y = fmaf(v0.y, w0, a0.y);
        a0.z = fmaf(v0.z, w0, a0.z); a0.w = fmaf(v0.w, w0, a0.w);
    }
    a0.x += a1.x; a0.y += a1.y; a0.z += a1.z; a0.w += a1.w;

    float dd = dis[node];
    float4 self = xt4[(size_t)node * 64 + c4];
    float4 b = reinterpret_cast<const float4*>(bias)[c4];
    float4 r;
    r.x = fmaf(dd, fmaf(self.x, dd, a0.x), b.x);
    r.y = fmaf(dd, fmaf(self.y, dd, a0.y), b.y);
    r.z = fmaf(dd, fmaf(self.z, dd, a0.z), b.z);
    r.w = fmaf(dd, fmaf(self.w, dd, a0.w), b.w);
    reinterpret_cast<float4*>(agg)[(size_t)node * 64 + c4] = r;
}

// ---------------- bf16x3 tensor-core GEMM (m16n8k16), double-buffered ---------
// a = hi + lo in bf16; D += ah*bh + ah*bl + al*bh. Error ~2^-16 per product.
// BM=128, BN=128, BK=32. Smem: A as [m][k-pair] bf16x2, B transposed [n][k-pair].

__device__ __forceinline__ uint32_t pack_bf(float lo, float hi) {
    uint32_t r;
    asm("cvt.rn.bf16x2.f32 %0, %1, %2;" : "=r"(r) : "f"(hi), "f"(lo));
    return r;
}

// (a0,a1) -> hi word + lo word (a0 in low half = even k)
__device__ __forceinline__ void split_pair(float a0, float a1, uint32_t& h, uint32_t& l) {
    h = pack_bf(a0, a1);
    float h0 = __uint_as_float(h << 16);
    float h1 = __uint_as_float(h & 0xFFFF0000u);
    l = pack_bf(a0 - h0, a1 - h1);
}

__device__ __forceinline__ void mma_bf16(float (&d)[4], const uint32_t (&a)[4],
                                         const uint32_t (&b)[2]) {
    asm("mma.sync.aligned.m16n8k16.row.col.f32.bf16.bf16.f32 "
        "{%0,%1,%2,%3}, {%4,%5,%6,%7}, {%8,%9}, {%0,%1,%2,%3};"
        : "+f"(d[0]), "+f"(d[1]), "+f"(d[2]), "+f"(d[3])
        : "r"(a[0]), "r"(a[1]), "r"(a[2]), "r"(a[3]), "r"(b[0]), "r"(b[1]));
}

#define KPS 16          // k-pairs per BK=32 stage
#define TSTRIDE 17      // row stride in words (16 + 1 pad)
#define TILE_WORDS (128 * TSTRIDE)       // 2176
#define STAGE_WORDS (4 * TILE_WORDS)     // As_hi, As_lo, Bs_hi, Bs_lo
#define GEMM_SMEM_BYTES (2 * STAGE_WORDS * 4)   // 69632

template<bool SPLIT_A, bool RELU_IN, bool ADD_BIAS>
__global__ void __launch_bounds__(256, 2)
mma_gemm(const float* __restrict__ A, const float* __restrict__ A2,
         const float* __restrict__ B,
         const float* __restrict__ bias, float* __restrict__ C,
         int M, int N, int K) {
    extern __shared__ uint32_t sm[];

    const int tid  = threadIdx.x;
    const int lane = tid & 31;
    const int warp = tid >> 5;
    const int wm = warp & 3;
    const int wn = warp >> 2;
    const int g = lane >> 2;
    const int t = lane & 3;
    const int bm = blockIdx.y * 128;
    const int bn = blockIdx.x * 128;

    float acc[2][8][4];
#pragma unroll
    for (int mi = 0; mi < 2; mi++)
#pragma unroll
        for (int ni = 0; ni < 8; ni++)
#pragma unroll
            for (int r = 0; r < 4; r++) acc[mi][ni][r] = 0.0f;

    float4 pa[4];        // A[m][k4..k4+3]
    float4 pb[4];        // {B[k][n0], B[k][n1], B[k+1][n0], B[k+1][n1]}

    auto load_tiles = [&](int k0) {
#pragma unroll
        for (int i = 0; i < 4; i++) {
            int idx = i * 256 + tid;
            int m  = idx >> 3;                 // 0..127
            int col = k0 + ((idx & 7) << 2);   // k, float4-aligned
            int gm = bm + m;
            if (gm < M) {
                if (SPLIT_A) {
                    pa[i] = (col < D_IN)
                        ? *reinterpret_cast<const float4*>(A  + (size_t)gm * D_IN  + col)
                        : *reinterpret_cast<const float4*>(A2 + (size_t)gm * D_RNI + (col - D_IN));
                } else {
                    pa[i] = *reinterpret_cast<const float4*>(A + (size_t)gm * K + col);
                }
            } else {
                pa[i] = make_float4(0.f, 0.f, 0.f, 0.f);
            }
        }
#pragma unroll
        for (int i = 0; i < 4; i++) {
            int idx = i * 256 + tid;
            int kp = idx >> 6;                 // 0..15
            int np = idx & 63;                 // n-pair 0..63
            int krow = k0 + 2 * kp;
            const float* p0 = B + (size_t)krow * N + bn + 2 * np;
            float2 v0 = *reinterpret_cast<const float2*>(p0);
            float2 v1 = *reinterpret_cast<const float2*>(p0 + N);
            pb[i] = make_float4(v0.x, v0.y, v1.x, v1.y);
        }
    };

    auto store_tiles = [&](int s) {
        uint32_t* As_hi = sm + s * STAGE_WORDS;
        uint32_t* As_lo = As_hi + TILE_WORDS;
        uint32_t* Bs_hi = As_hi + 2 * TILE_WORDS;
        uint32_t* Bs_lo = As_hi + 3 * TILE_WORDS;
#pragma unroll
        for (int i = 0; i < 4; i++) {
            int idx = i * 256 + tid;
            int m  = idx >> 3;
            int kp = (idx & 7) << 1;           // k-pair index (even)
            float4 v = pa[i];
            if (RELU_IN) {
                v.x = fmaxf(v.x, 0.f); v.y = fmaxf(v.y, 0.f);
                v.z = fmaxf(v.z, 0.f); v.w = fmaxf(v.w, 0.f);
            }
            uint32_t h0, l0, h1, l1;
            split_pair(v.x, v.y, h0, l0);
            split_pair(v.z, v.w, h1, l1);
            int base = m * TSTRIDE + kp;
            As_hi[base] = h0; As_hi[base + 1] = h1;
            As_lo[base] = l0; As_lo[base + 1] = l1;
        }
#pragma unroll
        for (int i = 0; i < 4; i++) {
            int idx = i * 256 + tid;
            int kp = idx >> 6;
            int np = idx & 63;
            float4 v = pb[i];
            uint32_t h0, l0, h1, l1;
            split_pair(v.x, v.z, h0, l0);      // column n0: {k even, k odd}
            split_pair(v.y, v.w, h1, l1);      // column n1
            int b0 = (2 * np) * TSTRIDE + kp;
            int b1 = b0 + TSTRIDE;
            Bs_hi[b0] = h0; Bs_hi[b1] = h1;
            Bs_lo[b0] = l0; Bs_lo[b1] = l1;
        }
    };

    auto compute = [&](int s) {
        uint32_t* As_hi = sm + s * STAGE_WORDS;
        uint32_t* As_lo = As_hi + TILE_WORDS;
        uint32_t* Bs_hi = As_hi + 2 * TILE_WORDS;
        uint32_t* Bs_lo = As_hi + 3 * TILE_WORDS;
#pragma unroll
        for (int kk = 0; kk < 2; kk++) {       // two K=16 slices
            int kpb = kk * 8;
            uint32_t ah[2][4], al[2][4];
#pragma unroll
            for (int mi = 0; mi < 2; mi++) {
                int r0 = (wm * 32 + mi * 16 + g) * TSTRIDE;
                int r1 = r0 + 8 * TSTRIDE;
                int c0 = kpb + t;
                int c1 = c0 + 4;
                ah[mi][0] = As_hi[r0 + c0]; ah[mi][1] = As_hi[r1 + c0];
                ah[mi][2] = As_hi[r0 + c1]; ah[mi][3] = As_hi[r1 + c1];
                al[mi][0] = As_lo[r0 + c0]; al[mi][1] = As_lo[r1 + c0];
                al[mi][2] = As_lo[r0 + c1]; al[mi][3] = As_lo[r1 + c1];
            }
#pragma unroll
            for (int ni = 0; ni < 8; ni++) {
                int nrow = (wn * 64 + ni * 8 + g) * TSTRIDE;
                uint32_t bh[2] = { Bs_hi[nrow + kpb + t], Bs_hi[nrow + kpb + t + 4] };
                uint32_t bl[2] = { Bs_lo[nrow + kpb + t], Bs_lo[nrow + kpb + t + 4] };
#pragma unroll
                for (int mi = 0; mi < 2; mi++) {
                    mma_bf16(acc[mi][ni], ah[mi], bh);
                    mma_bf16(acc[mi][ni], ah[mi], bl);
                    mma_bf16(acc[mi][ni], al[mi], bh);
                }
            }
        }
    };

    // prologue: fill stage 0
    load_tiles(0);
    store_tiles(0);
    __syncthreads();

    int cur = 0;
    for (int k0 = 0; k0 < K; k0 += 32) {
        bool has_next = (k0 + 32 < K);
        if (has_next) load_tiles(k0 + 32);
        compute(cur);
        if (has_next) store_tiles(cur ^ 1);
        __syncthreads();
        cur ^= 1;
    }

#pragma unroll
    for (int mi = 0; mi < 2; mi++) {
#pragma unroll
        for (int ni = 0; ni < 8; ni++) {
            int row = bm + wm * 32 + mi * 16 + g;
            int col = bn + wn * 64 + ni * 8 + t * 2;
            float bx = 0.f, by = 0.f;
            if (ADD_BIAS) {
                float2 bb = *reinterpret_cast<const float2*>(bias + col);
                bx = bb.x; by = bb.y;
            }
            if (row < M) {
                float2 v = make_float2(acc[mi][ni][0] + bx, acc[mi][ni][1] + by);
                *reinterpret_cast<float2*>(C + (size_t)row * N + col) = v;
            }
            int row2 = row + 8;
            if (row2 < M) {
                float2 v = make_float2(acc[mi][ni][2] + bx, acc[mi][ni][3] + by);
                *reinterpret_cast<float2*>(C + (size_t)row2 * N + col) = v;
            }
        }
    }
}

// ---------------- launch ------------------------------------------------------
extern "C" void kernel_launch(void* const* d_in, const int* in_sizes, int n_in,
                              void* d_out, int out_size) {
    const float* x     = (const float*)d_in[0];
    const float* rni   = (const float*)d_in[1];
    const void*  ei    = d_in[2];
    const float* W1    = (const float*)d_in[3];
    const float* b1    = (const float*)d_in[4];
    const float* W2    = (const float*)d_in[5];
    const float* b2    = (const float*)d_in[6];
    const float* Wout  = (const float*)d_in[7];
    const float* bout  = (const float*)d_in[8];
    float* out = (float*)d_out;

    int n = in_sizes[0] / D_IN;
    int e = in_sizes[2] / 2;

    float *xt, *agg, *dis;
    int *deg, *row_start, *cursor, *csr_src;
    cudaGetSymbolAddress((void**)&xt,        g_xt);
    cudaGetSymbolAddress((void**)&agg,       g_agg);
    cudaGetSymbolAddress((void**)&dis,       g_dis);
    cudaGetSymbolAddress((void**)&deg,       g_deg);
    cudaGetSymbolAddress((void**)&row_start, g_rowstart);
    cudaGetSymbolAddress((void**)&cursor,    g_cursor);
    cudaGetSymbolAddress((void**)&csr_src,   g_csr_src);

    cudaFuncSetAttribute(mma_gemm<true,  false, false>, cudaFuncAttributeMaxDynamicSharedMemorySize, GEMM_SMEM_BYTES);
    cudaFuncSetAttribute(mma_gemm<false, true,  false>, cudaFuncAttributeMaxDynamicSharedMemorySize, GEMM_SMEM_BYTES);
    cudaFuncSetAttribute(mma_gemm<false, true,  true >, cudaFuncAttributeMaxDynamicSharedMemorySize, GEMM_SMEM_BYTES);

    // prep (4th kernel launch = mma_gemm for the ncu capture window)
    detect_kernel<<<1, 32>>>(ei, n);
    cudaMemsetAsync(deg, 0, (size_t)n * sizeof(int));
    count_deg_kernel<<<(e + 255) / 256, 256>>>(ei, deg, e, n);
    scan_dis_kernel<<<1, 1024>>>(deg, row_start, cursor, dis, n);

    dim3 gemm_grid(H / 128, (n + 127) / 128);
    int gather_grid = (n + 3) / 4;

    // layer 1 GEMM; CSR fill overlaps (only the gather needs it)
    mma_gemm<true, false, false><<<gemm_grid, 256, GEMM_SMEM_BYTES>>>(x, rni, W1, nullptr, xt, n, H, D_H0);
    csr_fill_kernel<<<(e + 255) / 256, 256>>>(ei, cursor, csr_src, e, n);
    gather_kernel<<<gather_grid, 256>>>(xt, dis, row_start, deg, csr_src, b1, agg, n);

    // layer 2
    mma_gemm<false, true, false><<<gemm_grid, 256, GEMM_SMEM_BYTES>>>(agg, nullptr, W2, nullptr, xt, n, H, H);
    gather_kernel<<<gather_grid, 256>>>(xt, dis, row_start, deg, csr_src, b2, agg, n);

    // output
    mma_gemm<false, true, true><<<gemm_grid, 256, GEMM_SMEM_BYTES>>>(agg, nullptr, Wout, bout, out, n, H, H);
}